// round 9
// baseline (speedup 1.0000x reference)
#include <cuda_runtime.h>

// ---------------- problem constants ----------------
#define Bsz 512
#define Ssz 1024
#define Isz 64
#define Hsz 256
#define Gsz 768   // 3*H

// ---------------- recurrence partition ----------------
#define NI   32            // batch groups
#define MBLK 16            // batch rows per group
#define NJ   4             // hidden-column slices
#define NCTA (NI*NJ)       // 128 persistent CTAs

#define WSTRIDE 192        // row stride (floats) for Wh^T tile [256][192]
#define HSTRIDE 16         // row stride (floats) for h^T tile  [256][16]
#define SMEM_GRU ((256*WSTRIDE + 256*HSTRIDE) * 4)   // 212992 bytes

// ---------------- gate_x GEMM tiling ----------------
#define GX_MT 128
#define GX_NT 192
#define GX_SMEM ((64*128 + 64*192) * 4)              // 81920 bytes

// ---------------- static scratch (no allocations allowed) ----------------
__device__ float g_gatex[1ULL * Ssz * Bsz * Gsz];    // [S][B][G]  ~1.61 GB
__device__ float g_h[2][Bsz][Hsz];                   // double-buffered hidden state
__device__ int   g_cnt[NI][Ssz];                     // per-group per-step arrival counters

// ---------------- helpers ----------------
__device__ __forceinline__ unsigned long long pk2(float a, float b) {
    unsigned long long r;
    asm("mov.b64 %0, {%1, %2};" : "=l"(r) : "f"(a), "f"(b));
    return r;
}
__device__ __forceinline__ float2 u2f2(unsigned long long v) {
    float2 r;
    asm("mov.b64 {%0, %1}, %2;" : "=f"(r.x), "=f"(r.y) : "l"(v));
    return r;
}
__device__ __forceinline__ void fma2(unsigned long long& d,
                                     unsigned long long a, unsigned long long b) {
    asm("fma.rn.f32x2 %0, %1, %2, %0;" : "+l"(d) : "l"(a), "l"(b));
}
__device__ __forceinline__ float sigf(float x) {
    return __fdividef(1.0f, 1.0f + __expf(-x));
}
__device__ __forceinline__ float tanhfast(float x) {
    float ax = fabsf(x);
    float e  = __expf(-2.0f * ax);
    float r  = __fdividef(1.0f - e, 1.0f + e);
    return copysignf(r, x);
}
__device__ __forceinline__ int ld_acq(const int* p) {
    int v;
    asm volatile("ld.acquire.gpu.global.b32 %0, [%1];" : "=r"(v) : "l"(p) : "memory");
    return v;
}
__device__ __forceinline__ void red_rel_add1(int* p) {
    asm volatile("red.release.gpu.global.add.s32 [%0], 1;" :: "l"(p) : "memory");
}
// L2-coherent (L1-bypassing) load/store for cross-CTA payload
__device__ __forceinline__ float4 ldcg4(const float* p) {
    float4 v;
    asm volatile("ld.global.cg.v4.f32 {%0,%1,%2,%3}, [%4];"
                 : "=f"(v.x), "=f"(v.y), "=f"(v.z), "=f"(v.w) : "l"(p) : "memory");
    return v;
}
__device__ __forceinline__ void stcg(float* p, float v) {
    asm volatile("st.global.cg.f32 [%0], %1;" :: "l"(p), "f"(v) : "memory");
}

// ---------------- kernel 0: per-replay state reset ----------------
__global__ void k_init() {
    int i = blockIdx.x * blockDim.x + threadIdx.x;
    if (i < NI * Ssz)      ((int*)g_cnt)[i] = 0;
    if (i < 2 * Bsz * Hsz) ((float*)g_h)[i] = 0.0f;
}

// ---------------- kernel 1: gate_x[s][b][g] = sum_i x[b][s][i] * Wx[g][i] ----------------
// grid 16384 = 4096 row-tiles (128 rows of r = b*1024+s) x 4 col-tiles (192 of 768 gates)
__global__ __launch_bounds__(256, 1)
void k_gatex(const float* __restrict__ x, const float* __restrict__ Wx) {
    extern __shared__ float sm[];
    float* xsT = sm;              // [64][128]  x^T tile
    float* wsT = sm + 64 * 128;   // [64][192]  Wx^T tile

    const int tid = threadIdx.x;
    const int r0  = (blockIdx.x >> 2) * GX_MT;
    const int g0  = (blockIdx.x & 3) * GX_NT;

    // load + transpose x tile (128 rows x 64 k)
    for (int t = tid; t < 128 * 16; t += 256) {
        int m = t >> 4, k4 = (t & 15) << 2;
        float4 v = *(const float4*)(x + (size_t)(r0 + m) * Isz + k4);
        xsT[(k4 + 0) * 128 + m] = v.x;
        xsT[(k4 + 1) * 128 + m] = v.y;
        xsT[(k4 + 2) * 128 + m] = v.z;
        xsT[(k4 + 3) * 128 + m] = v.w;
    }
    // load + transpose Wx tile (192 rows x 64 k)
    for (int t = tid; t < 192 * 16; t += 256) {
        int n = t >> 4, k4 = (t & 15) << 2;
        float4 v = *(const float4*)(Wx + (size_t)(g0 + n) * Isz + k4);
        wsT[(k4 + 0) * 192 + n] = v.x;
        wsT[(k4 + 1) * 192 + n] = v.y;
        wsT[(k4 + 2) * 192 + n] = v.z;
        wsT[(k4 + 3) * 192 + n] = v.w;
    }
    __syncthreads();

    const int mb = (tid >> 4) * 8;   // 8 m-rows per thread
    const int nb = (tid & 15) * 12;  // 12 n-cols per thread (6 packed pairs)

    unsigned long long acc[8][6];
#pragma unroll
    for (int m = 0; m < 8; m++)
#pragma unroll
        for (int p = 0; p < 6; p++) acc[m][p] = 0ULL;

#pragma unroll 4
    for (int k = 0; k < 64; k++) {
        float4 xa = *(const float4*)&xsT[k * 128 + mb];
        float4 xb = *(const float4*)&xsT[k * 128 + mb + 4];
        ulonglong2 w0 = *(const ulonglong2*)&wsT[k * 192 + nb];
        ulonglong2 w1 = *(const ulonglong2*)&wsT[k * 192 + nb + 4];
        ulonglong2 w2 = *(const ulonglong2*)&wsT[k * 192 + nb + 8];
        unsigned long long wv[6] = {w0.x, w0.y, w1.x, w1.y, w2.x, w2.y};
        float xm[8] = {xa.x, xa.y, xa.z, xa.w, xb.x, xb.y, xb.z, xb.w};
#pragma unroll
        for (int m = 0; m < 8; m++) {
            unsigned long long xx = pk2(xm[m], xm[m]);
#pragma unroll
            for (int p = 0; p < 6; p++) fma2(acc[m][p], xx, wv[p]);
        }
    }

    // store: gate_x[s][b][g]
#pragma unroll
    for (int m = 0; m < 8; m++) {
        int r = r0 + mb + m;
        int b = r >> 10, s = r & 1023;
        float* op = g_gatex + ((size_t)s * Bsz + b) * Gsz + g0 + nb;
#pragma unroll
        for (int q = 0; q < 3; q++) {
            float2 a = u2f2(acc[m][2 * q]);
            float2 c = u2f2(acc[m][2 * q + 1]);
            *(float4*)(op + 4 * q) = make_float4(a.x, a.y, c.x, c.y);
        }
    }
}

// ---------------- kernel 2: persistent GRU recurrence ----------------
// CTA (gi, j): batch rows [gi*16, gi*16+16), hidden cols [j*64, j*64+64).
// Wh slice resident in smem, interleaved wsT[k][hc*3+g] = Wh[g*256+jc+hc][k].
// 128 threads = 2 m-groups (8 rows) x 64 hidden cols (3 gates each).
// Cross-CTA h exchange via L2 (.cg) + per-group release/acquire counters.
__global__ __launch_bounds__(128, 1)
void k_gru(const float* __restrict__ Wh, const float* __restrict__ bias) {
    extern __shared__ float sm[];
    float* wsT = sm;                   // [256][WSTRIDE]
    float* hsT = sm + 256 * WSTRIDE;   // [256][HSTRIDE]

    const int tid = threadIdx.x;
    const int gi  = blockIdx.x >> 2;
    const int j   = blockIdx.x & 3;
    const int b0  = gi * MBLK;
    const int jc  = j * 64;
    const int mg  = tid >> 6;          // m-group 0/1 -> rows m0..m0+7
    const int nc  = tid & 63;          // local hidden col 0..63
    const int m0  = mg * 8;
    const int nc3 = nc * 3;

    // load Wh slice, transposed + gate-interleaved (one-time).
    // K = 256 -> 192 rows x 64 float4-groups  (R8 BUG: bound was 192*16, k only [0,64))
    for (int t = tid; t < 192 * 64; t += 128) {
        int row = t >> 6, k4 = (t & 63) << 2;
        int g = row / 64, hc = row % 64;
        float4 v = *(const float4*)(Wh + (size_t)(g * Hsz + jc + hc) * Hsz + k4);
        int n = hc * 3 + g;
        wsT[(k4 + 0) * WSTRIDE + n] = v.x;
        wsT[(k4 + 1) * WSTRIDE + n] = v.y;
        wsT[(k4 + 2) * WSTRIDE + n] = v.z;
        wsT[(k4 + 3) * WSTRIDE + n] = v.w;
    }
    const float br = bias[0 * Hsz + jc + nc];
    const float bz = bias[1 * Hsz + jc + nc];
    const float bh = bias[2 * Hsz + jc + nc];
    __syncthreads();

    int* cnt = &g_cnt[gi][0];

    for (int s = 0; s < Ssz; s++) {
        const float* hprev = &g_h[s & 1][0][0];
        float*       hnext = &g_h[(s + 1) & 1][0][0];

        // prefetch this step's input gates (independent of the sync)
        float gxv[3][8];
        {
            const float* gxb = g_gatex + ((size_t)s * Bsz + b0 + m0) * Gsz + jc + nc;
#pragma unroll
            for (int m = 0; m < 8; m++) {
                gxv[0][m] = __ldg(gxb + m * Gsz + 0);
                gxv[1][m] = __ldg(gxb + m * Gsz + 256);
                gxv[2][m] = __ldg(gxb + m * Gsz + 512);
            }
        }

        // wait for all 4 slices of this group's h from the previous step
        if (s > 0) {
            if (tid == 0) {
                while (ld_acq(&cnt[s - 1]) < NJ) { }
            }
            __syncthreads();
        }

        // transpose h into hsT via L2-coherent loads: hsT[k][m] = h[b0+m][k]
#pragma unroll
        for (int it = 0; it < 8; it++) {
            int idx = tid + it * 128;
            int m = idx & 15, kq = idx >> 4;     // kq in 0..63
            float4 v = ldcg4(hprev + (size_t)(b0 + m) * Hsz + kq * 4);
            hsT[(kq * 4 + 0) * HSTRIDE + m] = v.x;
            hsT[(kq * 4 + 1) * HSTRIDE + m] = v.y;
            hsT[(kq * 4 + 2) * HSTRIDE + m] = v.z;
            hsT[(kq * 4 + 3) * HSTRIDE + m] = v.w;
        }
        __syncthreads();

        // GEMM: 8 rows x 3 gate-cols per thread, f32x2 over row pairs
        unsigned long long acc[4][3];
#pragma unroll
        for (int p = 0; p < 4; p++)
#pragma unroll
            for (int q = 0; q < 3; q++) acc[p][q] = 0ULL;

#pragma unroll 4
        for (int k = 0; k < 256; k++) {
            const float* hr_ = &hsT[k * HSTRIDE + m0];
            unsigned long long hv0 = *(const unsigned long long*)(hr_ + 0);
            unsigned long long hv1 = *(const unsigned long long*)(hr_ + 2);
            unsigned long long hv2 = *(const unsigned long long*)(hr_ + 4);
            unsigned long long hv3 = *(const unsigned long long*)(hr_ + 6);
            const float* wr_ = &wsT[k * WSTRIDE + nc3];
            unsigned long long W0 = pk2(wr_[0], wr_[0]);
            unsigned long long W1 = pk2(wr_[1], wr_[1]);
            unsigned long long W2 = pk2(wr_[2], wr_[2]);
            fma2(acc[0][0], hv0, W0); fma2(acc[0][1], hv0, W1); fma2(acc[0][2], hv0, W2);
            fma2(acc[1][0], hv1, W0); fma2(acc[1][1], hv1, W1); fma2(acc[1][2], hv1, W2);
            fma2(acc[2][0], hv2, W0); fma2(acc[2][1], hv2, W1); fma2(acc[2][2], hv2, W2);
            fma2(acc[3][0], hv3, W0); fma2(acc[3][1], hv3, W1); fma2(acc[3][2], hv3, W2);
        }

        // GRU pointwise update + L2-coherent write of h'
#pragma unroll
        for (int p = 0; p < 4; p++) {
            float2 ar = u2f2(acc[p][0]);
            float2 az = u2f2(acc[p][1]);
            float2 ah = u2f2(acc[p][2]);
#pragma unroll
            for (int rr = 0; rr < 2; rr++) {
                int ml = 2 * p + rr;               // local row within m-group
                float hr = rr ? ar.y : ar.x;
                float hz = rr ? az.y : az.x;
                float hh = rr ? ah.y : ah.x;
                float rg = sigf(gxv[0][ml] + hr + br);
                float zg = sigf(gxv[1][ml] + hz + bz);
                float ng = tanhfast(gxv[2][ml] + rg * hh + bh);
                float hpv = hsT[(jc + nc) * HSTRIDE + m0 + ml];
                float hy = ng + zg * (hpv - ng);
                stcg(hnext + (size_t)(b0 + m0 + ml) * Hsz + jc + nc, hy);
            }
        }

        __threadfence();
        __syncthreads();
        if (tid == 0) red_rel_add1(&cnt[s]);
    }
}

// ---------------- kernel 3: logits = h_T @ fc_w^T + fc_b ----------------
__global__ void k_fc(const float* __restrict__ fc_w, const float* __restrict__ fc_b,
                     float* __restrict__ out) {
    int b = blockIdx.x;
    int c = threadIdx.x >> 5;
    int lane = threadIdx.x & 31;
    const float* h = &g_h[0][b][0];   // final h lives in buffer 0 (1024 is even)
    float sum = 0.0f;
#pragma unroll
    for (int k = lane; k < Hsz; k += 32)
        sum += h[k] * fc_w[c * Hsz + k];
#pragma unroll
    for (int o = 16; o > 0; o >>= 1)
        sum += __shfl_xor_sync(0xffffffffu, sum, o);
    if (lane == 0)
        out[b * 10 + c] = sum + fc_b[c];
}

// ---------------- launch ----------------
extern "C" void kernel_launch(void* const* d_in, const int* in_sizes, int n_in,
                              void* d_out, int out_size) {
    // Map inputs by UNIQUE element counts (robust to metadata ordering).
    const float *x = 0, *Wx = 0, *Wh = 0, *bias = 0, *fc_w = 0, *fc_b = 0;
    for (int i = 0; i < n_in; i++) {
        switch (in_sizes[i]) {
            case Bsz * Ssz * Isz: x    = (const float*)d_in[i]; break;  // 33554432
            case Gsz * Isz:       Wx   = (const float*)d_in[i]; break;  // 49152
            case Gsz * Hsz:       Wh   = (const float*)d_in[i]; break;  // 196608
            case Gsz:             bias = (const float*)d_in[i]; break;  // 768
            case 10 * Hsz:        fc_w = (const float*)d_in[i]; break;  // 2560
            case 10:              fc_b = (const float*)d_in[i]; break;  // 10
            default: break;
        }
    }
    if (!x || !Wx || !Wh || !bias || !fc_w || !fc_b) {
        x    = (const float*)d_in[0];
        Wx   = (const float*)d_in[1];
        Wh   = (const float*)d_in[2];
        bias = (const float*)d_in[3];
        fc_w = (const float*)d_in[4];
        fc_b = (const float*)d_in[5];
    }
    float* out = (float*)d_out;

    cudaFuncSetAttribute(k_gatex, cudaFuncAttributeMaxDynamicSharedMemorySize, GX_SMEM);
    cudaFuncSetAttribute(k_gru,   cudaFuncAttributeMaxDynamicSharedMemorySize, SMEM_GRU);

    k_init<<<1024, 256>>>();
    k_gatex<<<16384, 256, GX_SMEM>>>(x, Wx);
    k_gru<<<NCTA, 128, SMEM_GRU>>>(Wh, bias);
    k_fc<<<512, 320>>>(fc_w, fc_b, out);
}

// round 10
// speedup vs baseline: 1.0836x; 1.0836x over previous
#include <cuda_runtime.h>

// ---------------- problem constants ----------------
#define Bsz 512
#define Ssz 1024
#define Isz 64
#define Hsz 256
#define Gsz 768   // 3*H

// ---------------- recurrence partition ----------------
#define NI   32            // batch groups
#define MBLK 16            // batch rows per group
#define NJ   4             // hidden-column slices
#define NCTA (NI*NJ)       // 128 persistent CTAs

#define WSTRIDE 192        // row stride (floats) for Wh^T tile [256][192]
#define HSTRIDE 18         // padded row stride (floats) for h^T tile [256][18] (2-way bank conflicts max)
#define SMEM_GRU ((256*WSTRIDE + 256*HSTRIDE) * 4)   // 215040 bytes

// ---------------- gate_x GEMM tiling ----------------
#define GX_MT 128
#define GX_NT 192
#define GX_SMEM ((64*128 + 64*192) * 4)              // 81920 bytes

// ---------------- static scratch (no allocations allowed) ----------------
__device__ float g_gatex[1ULL * Ssz * Bsz * Gsz];    // [S][B][G]  ~1.61 GB
__device__ float g_h[2][Bsz][Hsz];                   // double-buffered hidden state
__device__ int   g_cnt[NI][Ssz];                     // per-group per-step arrival counters

// ---------------- helpers ----------------
__device__ __forceinline__ unsigned long long pk2(float a, float b) {
    unsigned long long r;
    asm("mov.b64 %0, {%1, %2};" : "=l"(r) : "f"(a), "f"(b));
    return r;
}
__device__ __forceinline__ float2 u2f2(unsigned long long v) {
    float2 r;
    asm("mov.b64 {%0, %1}, %2;" : "=f"(r.x), "=f"(r.y) : "l"(v));
    return r;
}
__device__ __forceinline__ void fma2(unsigned long long& d,
                                     unsigned long long a, unsigned long long b) {
    asm("fma.rn.f32x2 %0, %1, %2, %0;" : "+l"(d) : "l"(a), "l"(b));
}
// MUFU.TANH-based activations (1 MUFU each instead of exp+div chains)
__device__ __forceinline__ float tanhA(float x) {
    float y;
    asm("tanh.approx.f32 %0, %1;" : "=f"(y) : "f"(x));
    return y;
}
__device__ __forceinline__ float sigA(float x) {
    return fmaf(tanhA(0.5f * x), 0.5f, 0.5f);
}
__device__ __forceinline__ int ld_acq(const int* p) {
    int v;
    asm volatile("ld.acquire.gpu.global.b32 %0, [%1];" : "=r"(v) : "l"(p) : "memory");
    return v;
}
__device__ __forceinline__ void red_rel_add1(int* p) {
    asm volatile("red.release.gpu.global.add.s32 [%0], 1;" :: "l"(p) : "memory");
}
// L2-coherent (L1-bypassing) load/store for cross-CTA payload
__device__ __forceinline__ float4 ldcg4(const float* p) {
    float4 v;
    asm volatile("ld.global.cg.v4.f32 {%0,%1,%2,%3}, [%4];"
                 : "=f"(v.x), "=f"(v.y), "=f"(v.z), "=f"(v.w) : "l"(p) : "memory");
    return v;
}
__device__ __forceinline__ void stcg(float* p, float v) {
    asm volatile("st.global.cg.f32 [%0], %1;" :: "l"(p), "f"(v) : "memory");
}

// inner-product slab over k-range [k0,k1): 8 rows x 3 gate-cols per thread
__device__ __forceinline__ void gemm_range(const float* __restrict__ hsT,
                                           const float* __restrict__ wsT,
                                           int k0, int k1, int m0, int nc3,
                                           unsigned long long acc[4][3]) {
#pragma unroll 4
    for (int k = k0; k < k1; k++) {
        const float* hr_ = &hsT[k * HSTRIDE + m0];
        unsigned long long hv0 = *(const unsigned long long*)(hr_ + 0);
        unsigned long long hv1 = *(const unsigned long long*)(hr_ + 2);
        unsigned long long hv2 = *(const unsigned long long*)(hr_ + 4);
        unsigned long long hv3 = *(const unsigned long long*)(hr_ + 6);
        const float* wr_ = &wsT[k * WSTRIDE + nc3];
        unsigned long long W0 = pk2(wr_[0], wr_[0]);
        unsigned long long W1 = pk2(wr_[1], wr_[1]);
        unsigned long long W2 = pk2(wr_[2], wr_[2]);
        fma2(acc[0][0], hv0, W0); fma2(acc[0][1], hv0, W1); fma2(acc[0][2], hv0, W2);
        fma2(acc[1][0], hv1, W0); fma2(acc[1][1], hv1, W1); fma2(acc[1][2], hv1, W2);
        fma2(acc[2][0], hv2, W0); fma2(acc[2][1], hv2, W1); fma2(acc[2][2], hv2, W2);
        fma2(acc[3][0], hv3, W0); fma2(acc[3][1], hv3, W1); fma2(acc[3][2], hv3, W2);
    }
}

// ---------------- no-op kernels: align ncu's -s 5 -c 1 onto k_gru ----------------
__global__ void k_nop() {}

// ---------------- kernel 0: per-replay state reset ----------------
__global__ void k_init() {
    int i = blockIdx.x * blockDim.x + threadIdx.x;
    if (i < NI * Ssz)      ((int*)g_cnt)[i] = 0;
    if (i < 2 * Bsz * Hsz) ((float*)g_h)[i] = 0.0f;
}

// ---------------- kernel 1: gate_x[s][b][g] = sum_i x[b][s][i] * Wx[g][i] ----------------
__global__ __launch_bounds__(256, 1)
void k_gatex(const float* __restrict__ x, const float* __restrict__ Wx) {
    extern __shared__ float sm[];
    float* xsT = sm;              // [64][128]  x^T tile
    float* wsT = sm + 64 * 128;   // [64][192]  Wx^T tile

    const int tid = threadIdx.x;
    const int r0  = (blockIdx.x >> 2) * GX_MT;
    const int g0  = (blockIdx.x & 3) * GX_NT;

    for (int t = tid; t < 128 * 16; t += 256) {
        int m = t >> 4, k4 = (t & 15) << 2;
        float4 v = *(const float4*)(x + (size_t)(r0 + m) * Isz + k4);
        xsT[(k4 + 0) * 128 + m] = v.x;
        xsT[(k4 + 1) * 128 + m] = v.y;
        xsT[(k4 + 2) * 128 + m] = v.z;
        xsT[(k4 + 3) * 128 + m] = v.w;
    }
    for (int t = tid; t < 192 * 16; t += 256) {
        int n = t >> 4, k4 = (t & 15) << 2;
        float4 v = *(const float4*)(Wx + (size_t)(g0 + n) * Isz + k4);
        wsT[(k4 + 0) * 192 + n] = v.x;
        wsT[(k4 + 1) * 192 + n] = v.y;
        wsT[(k4 + 2) * 192 + n] = v.z;
        wsT[(k4 + 3) * 192 + n] = v.w;
    }
    __syncthreads();

    const int mb = (tid >> 4) * 8;
    const int nb = (tid & 15) * 12;

    unsigned long long acc[8][6];
#pragma unroll
    for (int m = 0; m < 8; m++)
#pragma unroll
        for (int p = 0; p < 6; p++) acc[m][p] = 0ULL;

#pragma unroll 4
    for (int k = 0; k < 64; k++) {
        float4 xa = *(const float4*)&xsT[k * 128 + mb];
        float4 xb = *(const float4*)&xsT[k * 128 + mb + 4];
        ulonglong2 w0 = *(const ulonglong2*)&wsT[k * 192 + nb];
        ulonglong2 w1 = *(const ulonglong2*)&wsT[k * 192 + nb + 4];
        ulonglong2 w2 = *(const ulonglong2*)&wsT[k * 192 + nb + 8];
        unsigned long long wv[6] = {w0.x, w0.y, w1.x, w1.y, w2.x, w2.y};
        float xm[8] = {xa.x, xa.y, xa.z, xa.w, xb.x, xb.y, xb.z, xb.w};
#pragma unroll
        for (int m = 0; m < 8; m++) {
            unsigned long long xx = pk2(xm[m], xm[m]);
#pragma unroll
            for (int p = 0; p < 6; p++) fma2(acc[m][p], xx, wv[p]);
        }
    }

#pragma unroll
    for (int m = 0; m < 8; m++) {
        int r = r0 + mb + m;
        int b = r >> 10, s = r & 1023;
        float* op = g_gatex + ((size_t)s * Bsz + b) * Gsz + g0 + nb;
#pragma unroll
        for (int q = 0; q < 3; q++) {
            float2 a = u2f2(acc[m][2 * q]);
            float2 c = u2f2(acc[m][2 * q + 1]);
            *(float4*)(op + 4 * q) = make_float4(a.x, a.y, c.x, c.y);
        }
    }
}

// ---------------- kernel 2: persistent GRU recurrence ----------------
// CTA (gi, j): batch rows [gi*16, gi*16+16), hidden cols [j*64, j*64+64).
// Own h-slice stays resident in hsT (written at epilogue) -> 25% of next
// step's GEMM runs before the peer wait. Peer slices arrive via L2 (.cg)
// + per-group release/acquire counters (bar.sync + red.release publication).
__global__ __launch_bounds__(128, 1)
void k_gru(const float* __restrict__ Wh, const float* __restrict__ bias) {
    extern __shared__ float sm[];
    float* wsT = sm;                   // [256][WSTRIDE]
    float* hsT = sm + 256 * WSTRIDE;   // [256][HSTRIDE]

    const int tid = threadIdx.x;
    const int gi  = blockIdx.x >> 2;
    const int j   = blockIdx.x & 3;
    const int b0  = gi * MBLK;
    const int jc  = j * 64;
    const int mg  = tid >> 6;          // m-group 0/1 -> rows m0..m0+7
    const int nc  = tid & 63;          // local hidden col 0..63
    const int m0  = mg * 8;
    const int nc3 = nc * 3;

    // load Wh slice, transposed + gate-interleaved (K=256: 192 rows x 64 float4-groups)
    for (int t = tid; t < 192 * 64; t += 128) {
        int row = t >> 6, k4 = (t & 63) << 2;
        int g = row / 64, hc = row % 64;
        float4 v = *(const float4*)(Wh + (size_t)(g * Hsz + jc + hc) * Hsz + k4);
        int n = hc * 3 + g;
        wsT[(k4 + 0) * WSTRIDE + n] = v.x;
        wsT[(k4 + 1) * WSTRIDE + n] = v.y;
        wsT[(k4 + 2) * WSTRIDE + n] = v.z;
        wsT[(k4 + 3) * WSTRIDE + n] = v.w;
    }
    // zero h tile (h0 = 0; own slice is maintained locally from here on)
    for (int t = tid; t < 256 * HSTRIDE; t += 128) hsT[t] = 0.0f;

    const float br = bias[0 * Hsz + jc + nc];
    const float bz = bias[1 * Hsz + jc + nc];
    const float bh = bias[2 * Hsz + jc + nc];
    __syncthreads();

    int* cnt = &g_cnt[gi][0];
    const int jq = j * 16;             // own kq range [jq, jq+16)

    for (int s = 0; s < Ssz; s++) {
        const float* hprev = &g_h[s & 1][0][0];
        float*       hnext = &g_h[(s + 1) & 1][0][0];

        // prefetch this step's input gates (long-latency DRAM, consumed in epilogue)
        float gxv[3][8];
        {
            const float* gxb = g_gatex + ((size_t)s * Bsz + b0 + m0) * Gsz + jc + nc;
#pragma unroll
            for (int m = 0; m < 8; m++) {
                gxv[0][m] = __ldg(gxb + m * Gsz + 0);
                gxv[1][m] = __ldg(gxb + m * Gsz + 256);
                gxv[2][m] = __ldg(gxb + m * Gsz + 512);
            }
        }

        unsigned long long acc[4][3];
#pragma unroll
        for (int p = 0; p < 4; p++)
#pragma unroll
            for (int q = 0; q < 3; q++) acc[p][q] = 0ULL;

        // part 1: own-slice GEMM (hsT rows [jc, jc+64) are already current)
        gemm_range(hsT, wsT, jc, jc + 64, m0, nc3, acc);

        // wait for the 3 peer slices, then transpose them into hsT
        if (s > 0) {
            while (ld_acq(&cnt[s - 1]) < NJ) { }
#pragma unroll
            for (int it = 0; it < 6; it++) {
                int idx = tid + it * 128;
                int m = idx & 15, kq = idx >> 4;          // kq' in [0,48)
                kq += (kq >= jq) ? 16 : 0;                // skip own 16 kq-groups
                float4 v = ldcg4(hprev + (size_t)(b0 + m) * Hsz + kq * 4);
                hsT[(kq * 4 + 0) * HSTRIDE + m] = v.x;
                hsT[(kq * 4 + 1) * HSTRIDE + m] = v.y;
                hsT[(kq * 4 + 2) * HSTRIDE + m] = v.z;
                hsT[(kq * 4 + 3) * HSTRIDE + m] = v.w;
            }
        }
        __syncthreads();

        // part 2: peer-slice GEMM
        gemm_range(hsT, wsT, 0, jc, m0, nc3, acc);
        gemm_range(hsT, wsT, jc + 64, 256, m0, nc3, acc);

        // GRU pointwise update; publish h' to L2 and refresh own smem slice
#pragma unroll
        for (int p = 0; p < 4; p++) {
            float2 ar = u2f2(acc[p][0]);
            float2 az = u2f2(acc[p][1]);
            float2 ah = u2f2(acc[p][2]);
#pragma unroll
            for (int rr = 0; rr < 2; rr++) {
                int ml = 2 * p + rr;
                float hr = rr ? ar.y : ar.x;
                float hz = rr ? az.y : az.x;
                float hh = rr ? ah.y : ah.x;
                float rg = sigA(gxv[0][ml] + hr + br);
                float zg = sigA(gxv[1][ml] + hz + bz);
                float ng = tanhA(gxv[2][ml] + rg * hh + bh);
                float hpv = hsT[(jc + nc) * HSTRIDE + m0 + ml];
                float hy = ng + zg * (hpv - ng);
                stcg(hnext + (size_t)(b0 + m0 + ml) * Hsz + jc + nc, hy);
                hsT[(jc + nc) * HSTRIDE + m0 + ml] = hy;
            }
        }

        __syncthreads();                 // all stores done (CTA scope)
        if (tid == 0) red_rel_add1(&cnt[s]);   // gpu-scope release publishes them
    }
}

// ---------------- kernel 3: logits = h_T @ fc_w^T + fc_b ----------------
__global__ void k_fc(const float* __restrict__ fc_w, const float* __restrict__ fc_b,
                     float* __restrict__ out) {
    int b = blockIdx.x;
    int c = threadIdx.x >> 5;
    int lane = threadIdx.x & 31;
    const float* h = &g_h[0][b][0];   // final h lives in buffer 0 (1024 is even)
    float sum = 0.0f;
#pragma unroll
    for (int k = lane; k < Hsz; k += 32)
        sum += h[k] * fc_w[c * Hsz + k];
#pragma unroll
    for (int o = 16; o > 0; o >>= 1)
        sum += __shfl_xor_sync(0xffffffffu, sum, o);
    if (lane == 0)
        out[b * 10 + c] = sum + fc_b[c];
}

// ---------------- launch ----------------
extern "C" void kernel_launch(void* const* d_in, const int* in_sizes, int n_in,
                              void* d_out, int out_size) {
    // Map inputs by UNIQUE element counts (robust to metadata ordering).
    const float *x = 0, *Wx = 0, *Wh = 0, *bias = 0, *fc_w = 0, *fc_b = 0;
    for (int i = 0; i < n_in; i++) {
        switch (in_sizes[i]) {
            case Bsz * Ssz * Isz: x    = (const float*)d_in[i]; break;  // 33554432
            case Gsz * Isz:       Wx   = (const float*)d_in[i]; break;  // 49152
            case Gsz * Hsz:       Wh   = (const float*)d_in[i]; break;  // 196608
            case Gsz:             bias = (const float*)d_in[i]; break;  // 768
            case 10 * Hsz:        fc_w = (const float*)d_in[i]; break;  // 2560
            case 10:              fc_b = (const float*)d_in[i]; break;  // 10
            default: break;
        }
    }
    if (!x || !Wx || !Wh || !bias || !fc_w || !fc_b) {
        x    = (const float*)d_in[0];
        Wx   = (const float*)d_in[1];
        Wh   = (const float*)d_in[2];
        bias = (const float*)d_in[3];
        fc_w = (const float*)d_in[4];
        fc_b = (const float*)d_in[5];
    }
    float* out = (float*)d_out;

    cudaFuncSetAttribute(k_gatex, cudaFuncAttributeMaxDynamicSharedMemorySize, GX_SMEM);
    cudaFuncSetAttribute(k_gru,   cudaFuncAttributeMaxDynamicSharedMemorySize, SMEM_GRU);

    // 3 no-op launches align ncu's "-s 5 -c 1" window onto k_gru (launch idx 5)
    k_nop<<<1, 32>>>();
    k_nop<<<1, 32>>>();
    k_nop<<<1, 32>>>();
    k_init<<<1024, 256>>>();
    k_gatex<<<16384, 256, GX_SMEM>>>(x, Wx);
    k_gru<<<NCTA, 128, SMEM_GRU>>>(Wh, bias);
    k_fc<<<512, 320>>>(fc_w, fc_b, out);
}